// round 13
// baseline (speedup 1.0000x reference)
#include <cuda_runtime.h>
#include <math.h>

#define Bv    128
#define Dv    128
#define NMEM  200000
#define K1v   2048
#define INV_T (1.0f / 0.07f)

#define OUTS_ELEMS  (6LL * Bv * K1v)
#define MEM_ELEMS   ((long long)NMEM * Dv)
#define NIDX        (Bv * K1v)          // 262144
#define SLOTS       12
#define OVER_CAP    65536
#define NBUILD_BLOCKS ((NIDX + 255) / 256)   // 1024

// -------- device scratch (static zero-init == valid empty state) --------
// g_cw[r]: bits [0:24) = count (atomicAdd), bits [24:32) = owner+1 (atomicOr).
__device__ unsigned int g_cw[NMEM];
__device__ int g_slots[(long long)NMEM * SLOTS];
__device__ int g_over [OVER_CAP];                  // 0 = empty, else ent+1

// ---------------------------------------------------------------------------
// Kernel 1: build inverse map + owner map, AND compute the 128 EMA rows.
// Blocks [0, NBUILD_BLOCKS): inverse map build.
// Blocks [NBUILD_BLOCKS, NBUILD_BLOCKS+Bv): one block per b, EMA update of
// out_banks row y[b] (only if b is the last occurrence -> .at[y].set wins).
// Build completes before main (same stream), so main can skip owned rows.
// ---------------------------------------------------------------------------
__global__ void build_kernel(const int* __restrict__ idx,
                             const int* __restrict__ y,
                             const float* __restrict__ l,
                             const float* __restrict__ ab,
                             const float* __restrict__ ori,
                             const float* __restrict__ comp,
                             const float* __restrict__ mem_l,
                             const float* __restrict__ mem_ab,
                             const float* __restrict__ mem_ori,
                             const float* __restrict__ mem_comp,
                             float* __restrict__ out_banks)
{
    if (blockIdx.x < NBUILD_BLOCKS) {
        const int tid = blockIdx.x * blockDim.x + threadIdx.x;
        if (tid < NIDX) {
            const int row = idx[tid];
            const unsigned int old = atomicAdd(&g_cw[row], 1u);
            const int pos = (int)(old & 0xFFFFFFu);
            if (pos < SLOTS) {
                g_slots[(long long)row * SLOTS + pos] = tid;
            } else {
                // astronomically rare: CAS-claim a sentinel slot
                for (int s = 0; s < OVER_CAP; ++s)
                    if (atomicCAS(&g_over[s], 0, tid + 1) == 0) break;
            }
        }
        // owner map: last occurrence of y wins
        if (tid < Bv) {
            const int yi = y[tid];
            bool last = true;
            for (int j = tid + 1; j < Bv; ++j)
                if (y[j] == yi) { last = false; break; }
            if (last) atomicOr(&g_cw[yi], (unsigned int)(tid + 1) << 24);
        }
        return;
    }

    // ---- EMA blocks: one per b ----
    const int b = blockIdx.x - NBUILD_BLOCKS;    // 0..127
    const int t = threadIdx.x;
    if (t >= Dv) return;

    const int yb = y[b];
    for (int j = b + 1; j < Bv; ++j)
        if (y[j] == yb) return;                  // a later b owns this row

    __shared__ float red[4][4];
    const float* vs[4] = {l, ab, ori, comp};
    const float* ms[4] = {mem_l, mem_ab, mem_ori, mem_comp};
    const long long row = yb;

    float p[4];
    #pragma unroll
    for (int m = 0; m < 4; ++m) {
        p[m] = ms[m][row * Dv + t] * 0.5f + vs[m][b * Dv + t] * 0.5f;
        float sq = p[m] * p[m];
        #pragma unroll
        for (int off = 16; off > 0; off >>= 1)
            sq += __shfl_xor_sync(0xFFFFFFFFu, sq, off);
        if ((t & 31) == 0) red[m][t >> 5] = sq;
    }
    __syncthreads();
    #pragma unroll
    for (int m = 0; m < 4; ++m) {
        const float inv = rsqrtf(red[m][0] + red[m][1] + red[m][2] + red[m][3]);
        out_banks[(long long)m * MEM_ELEMS + row * Dv + t] = p[m] * inv;
    }
}

// ---------------------------------------------------------------------------
// Kernel 2 (main): single streaming pass over all bank rows.
// One warp per row. Front batch: 4x LDG.128 (evict-first) + packed metadata
// + slot0 prefetch, all unconditional, before any branch or store.
// Owned rows (EMA, written by build) are skipped. No else-branch -> fewer regs.
// Metadata self-clean at the VERY END.
// ---------------------------------------------------------------------------
__global__ __launch_bounds__(256, 7) void main_kernel(
    const float* __restrict__ l,
    const float* __restrict__ ab,
    const float* __restrict__ ori,
    const float* __restrict__ comp,
    const float* __restrict__ mem_l,
    const float* __restrict__ mem_ab,
    const float* __restrict__ mem_ori,
    const float* __restrict__ mem_comp,
    const int*   __restrict__ idx,
    float* __restrict__ outs,
    float* __restrict__ out_banks)
{
    const int warp = threadIdx.x >> 5;
    const int lane = threadIdx.x & 31;
    const long long gw = (long long)blockIdx.x * 8 + warp;   // 0..199999
    const long long r  = gw;

    // ---- front batch: all independent loads, no branches, no stores ----
    const float4 wl  = __ldcs(reinterpret_cast<const float4*>(mem_l    + r * Dv) + lane);
    const float4 wab = __ldcs(reinterpret_cast<const float4*>(mem_ab   + r * Dv) + lane);
    const float4 wor = __ldcs(reinterpret_cast<const float4*>(mem_ori  + r * Dv) + lane);
    const float4 wco = __ldcs(reinterpret_cast<const float4*>(mem_comp + r * Dv) + lane);

    const unsigned int cw = g_cw[r];
    const int ent0 = g_slots[r * SLOTS];   // prefetch slot 0 (always valid)

    const int cnt = (int)(cw & 0xFFFFFFu);

    // ---- write output banks: plain copy; owned rows already written by build
    if ((cw >> 24) == 0u) {
        __stcs(reinterpret_cast<float4*>(out_banks + 0 * MEM_ELEMS + r * Dv) + lane, wl);
        __stcs(reinterpret_cast<float4*>(out_banks + 1 * MEM_ELEMS + r * Dv) + lane, wab);
        __stcs(reinterpret_cast<float4*>(out_banks + 2 * MEM_ELEMS + r * Dv) + lane, wor);
        __stcs(reinterpret_cast<float4*>(out_banks + 3 * MEM_ELEMS + r * Dv) + lane, wco);
    }

    // ---- dot products for every (b,k) referencing this row ----
    const int nent = cnt < SLOTS ? cnt : SLOTS;
    for (int e = 0; e < nent; ++e) {
        const int ent = (e == 0) ? ent0 : g_slots[r * SLOTS + e];
        const int b   = ent >> 11;          // ent / K1v
        const int k   = ent & (K1v - 1);

        const float4 vl  = __ldg(reinterpret_cast<const float4*>(l    + b * Dv) + lane);
        const float4 vab = __ldg(reinterpret_cast<const float4*>(ab   + b * Dv) + lane);
        const float4 vor = __ldg(reinterpret_cast<const float4*>(ori  + b * Dv) + lane);
        const float4 vco = __ldg(reinterpret_cast<const float4*>(comp + b * Dv) + lane);

        float s0 = wor.x*vl.x  + wor.y*vl.y  + wor.z*vl.z  + wor.w*vl.w;
        float s1 = wl.x *vab.x + wl.y *vab.y + wl.z *vab.z + wl.w *vab.w;
        float s2 = wab.x*vor.x + wab.y*vor.y + wab.z*vor.z + wab.w*vor.w;
        float s3 = wco.x*vab.x + wco.y*vab.y + wco.z*vab.z + wco.w*vab.w;
        float s4 = wco.x*vl.x  + wco.y*vl.y  + wco.z*vl.z  + wco.w*vl.w;
        float s5 = wor.x*vco.x + wor.y*vco.y + wor.z*vco.z + wor.w*vco.w;

        #pragma unroll
        for (int off = 16; off > 0; off >>= 1) {
            s0 += __shfl_xor_sync(0xFFFFFFFFu, s0, off);
            s1 += __shfl_xor_sync(0xFFFFFFFFu, s1, off);
            s2 += __shfl_xor_sync(0xFFFFFFFFu, s2, off);
            s3 += __shfl_xor_sync(0xFFFFFFFFu, s3, off);
            s4 += __shfl_xor_sync(0xFFFFFFFFu, s4, off);
            s5 += __shfl_xor_sync(0xFFFFFFFFu, s5, off);
        }
        if (lane == 0) {
            const long long base   = (long long)b * K1v + k;
            const long long stride = (long long)Bv * K1v;
            outs[0 * stride + base] = s0 * INV_T;
            outs[1 * stride + base] = s1 * INV_T;
            outs[2 * stride + base] = s2 * INV_T;
            outs[3 * stride + base] = s3 * INV_T;
            outs[4 * stride + base] = s4 * INV_T;
            outs[5 * stride + base] = s5 * INV_T;
        }
    }

    // ---- overflow entries (zero-sentinel; astronomically rare) ----
    if (gw < OVER_CAP) {
        const int e = g_over[gw];
        if (e != 0) {
            const int ent = e - 1;
            const int b   = ent >> 11;
            const int k   = ent & (K1v - 1);
            const long long row = idx[ent];

            const float4 ol  = reinterpret_cast<const float4*>(mem_l    + row * Dv)[lane];
            const float4 oab = reinterpret_cast<const float4*>(mem_ab   + row * Dv)[lane];
            const float4 oor = reinterpret_cast<const float4*>(mem_ori  + row * Dv)[lane];
            const float4 oco = reinterpret_cast<const float4*>(mem_comp + row * Dv)[lane];

            const float4 vl  = __ldg(reinterpret_cast<const float4*>(l    + b * Dv) + lane);
            const float4 vab = __ldg(reinterpret_cast<const float4*>(ab   + b * Dv) + lane);
            const float4 vor = __ldg(reinterpret_cast<const float4*>(ori  + b * Dv) + lane);
            const float4 vco = __ldg(reinterpret_cast<const float4*>(comp + b * Dv) + lane);

            float s0 = oor.x*vl.x  + oor.y*vl.y  + oor.z*vl.z  + oor.w*vl.w;
            float s1 = ol.x *vab.x + ol.y *vab.y + ol.z *vab.z + ol.w *vab.w;
            float s2 = oab.x*vor.x + oab.y*vor.y + oab.z*vor.z + oab.w*vor.w;
            float s3 = oco.x*vab.x + oco.y*vab.y + oco.z*vab.z + oco.w*vab.w;
            float s4 = oco.x*vl.x  + oco.y*vl.y  + oco.z*vl.z  + oco.w*vl.w;
            float s5 = oor.x*vco.x + oor.y*vco.y + oor.z*vco.z + oor.w*vco.w;

            #pragma unroll
            for (int off = 16; off > 0; off >>= 1) {
                s0 += __shfl_xor_sync(0xFFFFFFFFu, s0, off);
                s1 += __shfl_xor_sync(0xFFFFFFFFu, s1, off);
                s2 += __shfl_xor_sync(0xFFFFFFFFu, s2, off);
                s3 += __shfl_xor_sync(0xFFFFFFFFu, s3, off);
                s4 += __shfl_xor_sync(0xFFFFFFFFu, s4, off);
                s5 += __shfl_xor_sync(0xFFFFFFFFu, s5, off);
            }
            if (lane == 0) {
                const long long base   = (long long)b * K1v + k;
                const long long stride = (long long)Bv * K1v;
                outs[0 * stride + base] = s0 * INV_T;
                outs[1 * stride + base] = s1 * INV_T;
                outs[2 * stride + base] = s2 * INV_T;
                outs[3 * stride + base] = s3 * INV_T;
                outs[4 * stride + base] = s4 * INV_T;
                outs[5 * stride + base] = s5 * INV_T;
                g_over[gw] = 0;               // reset used sentinel
            }
        }
    }

    // ---- self-clean for next launch (VERY END: after all loads issued) ----
    if (lane == 0) g_cw[r] = 0u;
}

// ---------------------------------------------------------------------------
extern "C" void kernel_launch(void* const* d_in, const int* in_sizes, int n_in,
                              void* d_out, int out_size)
{
    const float* l        = (const float*)d_in[0];
    const float* ab       = (const float*)d_in[1];
    const float* ori      = (const float*)d_in[2];
    const float* comp     = (const float*)d_in[3];
    const int*   y        = (const int*)  d_in[4];
    const int*   idx      = (const int*)  d_in[5];
    const float* mem_l    = (const float*)d_in[6];
    const float* mem_ab   = (const float*)d_in[7];
    const float* mem_ori  = (const float*)d_in[8];
    const float* mem_comp = (const float*)d_in[9];

    float* out       = (float*)d_out;
    float* out_outs  = out;
    float* out_banks = out + OUTS_ELEMS;

    build_kernel<<<NBUILD_BLOCKS + Bv, 256>>>(idx, y, l, ab, ori, comp,
                                              mem_l, mem_ab, mem_ori, mem_comp,
                                              out_banks);
    main_kernel<<<NMEM / 8, 256>>>(l, ab, ori, comp,
                                   mem_l, mem_ab, mem_ori, mem_comp,
                                   idx, out_outs, out_banks);
}

// round 14
// speedup vs baseline: 1.1800x; 1.1800x over previous
#include <cuda_runtime.h>
#include <math.h>

#define Bv    128
#define Dv    128
#define NMEM  200000
#define K1v   2048
#define INV_T (1.0f / 0.07f)

#define OUTS_ELEMS  (6LL * Bv * K1v)
#define MEM_ELEMS   ((long long)NMEM * Dv)
#define NIDX        (Bv * K1v)          // 262144
#define SLOTS       12
#define OVER_CAP    65536
#define NBUILD_BLOCKS ((NIDX + 255) / 256)   // 1024

// -------- device scratch (static zero-init == valid empty state) --------
// g_cw[r]: bits [0:24) = count (atomicAdd), bits [24:32) = owner+1 (atomicOr).
__device__ unsigned int g_cw[NMEM];
__device__ int g_slots[(long long)NMEM * SLOTS];
__device__ int g_over [OVER_CAP];                  // 0 = empty, else ent+1

// ---------------------------------------------------------------------------
// Kernel 1: build inverse map + owner map, AND compute the 128 EMA rows.
// Blocks [0, NBUILD_BLOCKS): inverse map build.
// Blocks [NBUILD_BLOCKS, NBUILD_BLOCKS+Bv): one block per b, EMA update of
// out_banks row y[b] (only if b is the last occurrence -> .at[y].set wins).
// Build completes before main (same stream), so main can skip owned rows.
// ---------------------------------------------------------------------------
__global__ void build_kernel(const int* __restrict__ idx,
                             const int* __restrict__ y,
                             const float* __restrict__ l,
                             const float* __restrict__ ab,
                             const float* __restrict__ ori,
                             const float* __restrict__ comp,
                             const float* __restrict__ mem_l,
                             const float* __restrict__ mem_ab,
                             const float* __restrict__ mem_ori,
                             const float* __restrict__ mem_comp,
                             float* __restrict__ out_banks)
{
    if (blockIdx.x < NBUILD_BLOCKS) {
        const int tid = blockIdx.x * blockDim.x + threadIdx.x;
        if (tid < NIDX) {
            const int row = idx[tid];
            const unsigned int old = atomicAdd(&g_cw[row], 1u);
            const int pos = (int)(old & 0xFFFFFFu);
            if (pos < SLOTS) {
                g_slots[(long long)row * SLOTS + pos] = tid;
            } else {
                // astronomically rare: CAS-claim a sentinel slot
                for (int s = 0; s < OVER_CAP; ++s)
                    if (atomicCAS(&g_over[s], 0, tid + 1) == 0) break;
            }
        }
        // owner map: last occurrence of y wins
        if (tid < Bv) {
            const int yi = y[tid];
            bool last = true;
            for (int j = tid + 1; j < Bv; ++j)
                if (y[j] == yi) { last = false; break; }
            if (last) atomicOr(&g_cw[yi], (unsigned int)(tid + 1) << 24);
        }
        return;
    }

    // ---- EMA blocks: one per b ----
    const int b = blockIdx.x - NBUILD_BLOCKS;    // 0..127
    const int t = threadIdx.x;
    if (t >= Dv) return;

    const int yb = y[b];
    for (int j = b + 1; j < Bv; ++j)
        if (y[j] == yb) return;                  // a later b owns this row

    __shared__ float red[4][4];
    const float* vs[4] = {l, ab, ori, comp};
    const float* ms[4] = {mem_l, mem_ab, mem_ori, mem_comp};
    const long long row = yb;

    float p[4];
    #pragma unroll
    for (int m = 0; m < 4; ++m) {
        p[m] = ms[m][row * Dv + t] * 0.5f + vs[m][b * Dv + t] * 0.5f;
        float sq = p[m] * p[m];
        #pragma unroll
        for (int off = 16; off > 0; off >>= 1)
            sq += __shfl_xor_sync(0xFFFFFFFFu, sq, off);
        if ((t & 31) == 0) red[m][t >> 5] = sq;
    }
    __syncthreads();
    #pragma unroll
    for (int m = 0; m < 4; ++m) {
        const float inv = rsqrtf(red[m][0] + red[m][1] + red[m][2] + red[m][3]);
        out_banks[(long long)m * MEM_ELEMS + row * Dv + t] = p[m] * inv;
    }
}

// ---------------------------------------------------------------------------
// Kernel 2 (main): single streaming pass over all bank rows.
// One warp per row. Front batch: 4x LDG.128 (evict-first) + packed metadata
// + slot0 prefetch, all unconditional, before any branch or store.
// Owned rows (EMA, written by build) are skipped.
// __launch_bounds__(256, 6): regs ~40 keeps the 4-load front batch in flight
// (cap 7 / 32 regs serialized it -> R13 regression).
// Metadata self-clean at the VERY END.
// ---------------------------------------------------------------------------
__global__ __launch_bounds__(256, 6) void main_kernel(
    const float* __restrict__ l,
    const float* __restrict__ ab,
    const float* __restrict__ ori,
    const float* __restrict__ comp,
    const float* __restrict__ mem_l,
    const float* __restrict__ mem_ab,
    const float* __restrict__ mem_ori,
    const float* __restrict__ mem_comp,
    const int*   __restrict__ idx,
    float* __restrict__ outs,
    float* __restrict__ out_banks)
{
    const int warp = threadIdx.x >> 5;
    const int lane = threadIdx.x & 31;
    const long long gw = (long long)blockIdx.x * 8 + warp;   // 0..199999
    const long long r  = gw;

    // ---- front batch: all independent loads, no branches, no stores ----
    const float4 wl  = __ldcs(reinterpret_cast<const float4*>(mem_l    + r * Dv) + lane);
    const float4 wab = __ldcs(reinterpret_cast<const float4*>(mem_ab   + r * Dv) + lane);
    const float4 wor = __ldcs(reinterpret_cast<const float4*>(mem_ori  + r * Dv) + lane);
    const float4 wco = __ldcs(reinterpret_cast<const float4*>(mem_comp + r * Dv) + lane);

    const unsigned int cw = g_cw[r];
    const int ent0 = g_slots[r * SLOTS];   // prefetch slot 0 (always valid)

    const int cnt = (int)(cw & 0xFFFFFFu);

    // ---- write output banks: plain copy; owned rows already written by build
    if ((cw >> 24) == 0u) {
        __stcs(reinterpret_cast<float4*>(out_banks + 0 * MEM_ELEMS + r * Dv) + lane, wl);
        __stcs(reinterpret_cast<float4*>(out_banks + 1 * MEM_ELEMS + r * Dv) + lane, wab);
        __stcs(reinterpret_cast<float4*>(out_banks + 2 * MEM_ELEMS + r * Dv) + lane, wor);
        __stcs(reinterpret_cast<float4*>(out_banks + 3 * MEM_ELEMS + r * Dv) + lane, wco);
    }

    // ---- dot products for every (b,k) referencing this row ----
    const int nent = cnt < SLOTS ? cnt : SLOTS;
    for (int e = 0; e < nent; ++e) {
        const int ent = (e == 0) ? ent0 : g_slots[r * SLOTS + e];
        const int b   = ent >> 11;          // ent / K1v
        const int k   = ent & (K1v - 1);

        const float4 vl  = __ldg(reinterpret_cast<const float4*>(l    + b * Dv) + lane);
        const float4 vab = __ldg(reinterpret_cast<const float4*>(ab   + b * Dv) + lane);
        const float4 vor = __ldg(reinterpret_cast<const float4*>(ori  + b * Dv) + lane);
        const float4 vco = __ldg(reinterpret_cast<const float4*>(comp + b * Dv) + lane);

        float s0 = wor.x*vl.x  + wor.y*vl.y  + wor.z*vl.z  + wor.w*vl.w;
        float s1 = wl.x *vab.x + wl.y *vab.y + wl.z *vab.z + wl.w *vab.w;
        float s2 = wab.x*vor.x + wab.y*vor.y + wab.z*vor.z + wab.w*vor.w;
        float s3 = wco.x*vab.x + wco.y*vab.y + wco.z*vab.z + wco.w*vab.w;
        float s4 = wco.x*vl.x  + wco.y*vl.y  + wco.z*vl.z  + wco.w*vl.w;
        float s5 = wor.x*vco.x + wor.y*vco.y + wor.z*vco.z + wor.w*vco.w;

        #pragma unroll
        for (int off = 16; off > 0; off >>= 1) {
            s0 += __shfl_xor_sync(0xFFFFFFFFu, s0, off);
            s1 += __shfl_xor_sync(0xFFFFFFFFu, s1, off);
            s2 += __shfl_xor_sync(0xFFFFFFFFu, s2, off);
            s3 += __shfl_xor_sync(0xFFFFFFFFu, s3, off);
            s4 += __shfl_xor_sync(0xFFFFFFFFu, s4, off);
            s5 += __shfl_xor_sync(0xFFFFFFFFu, s5, off);
        }
        if (lane == 0) {
            const long long base   = (long long)b * K1v + k;
            const long long stride = (long long)Bv * K1v;
            outs[0 * stride + base] = s0 * INV_T;
            outs[1 * stride + base] = s1 * INV_T;
            outs[2 * stride + base] = s2 * INV_T;
            outs[3 * stride + base] = s3 * INV_T;
            outs[4 * stride + base] = s4 * INV_T;
            outs[5 * stride + base] = s5 * INV_T;
        }
    }

    // ---- overflow entries (zero-sentinel; astronomically rare) ----
    if (gw < OVER_CAP) {
        const int e = g_over[gw];
        if (e != 0) {
            const int ent = e - 1;
            const int b   = ent >> 11;
            const int k   = ent & (K1v - 1);
            const long long row = idx[ent];

            const float4 ol  = reinterpret_cast<const float4*>(mem_l    + row * Dv)[lane];
            const float4 oab = reinterpret_cast<const float4*>(mem_ab   + row * Dv)[lane];
            const float4 oor = reinterpret_cast<const float4*>(mem_ori  + row * Dv)[lane];
            const float4 oco = reinterpret_cast<const float4*>(mem_comp + row * Dv)[lane];

            const float4 vl  = __ldg(reinterpret_cast<const float4*>(l    + b * Dv) + lane);
            const float4 vab = __ldg(reinterpret_cast<const float4*>(ab   + b * Dv) + lane);
            const float4 vor = __ldg(reinterpret_cast<const float4*>(ori  + b * Dv) + lane);
            const float4 vco = __ldg(reinterpret_cast<const float4*>(comp + b * Dv) + lane);

            float s0 = oor.x*vl.x  + oor.y*vl.y  + oor.z*vl.z  + oor.w*vl.w;
            float s1 = ol.x *vab.x + ol.y *vab.y + ol.z *vab.z + ol.w *vab.w;
            float s2 = oab.x*vor.x + oab.y*vor.y + oab.z*vor.z + oab.w*vor.w;
            float s3 = oco.x*vab.x + oco.y*vab.y + oco.z*vab.z + oco.w*vab.w;
            float s4 = oco.x*vl.x  + oco.y*vl.y  + oco.z*vl.z  + oco.w*vl.w;
            float s5 = oor.x*vco.x + oor.y*vco.y + oor.z*vco.z + oor.w*vco.w;

            #pragma unroll
            for (int off = 16; off > 0; off >>= 1) {
                s0 += __shfl_xor_sync(0xFFFFFFFFu, s0, off);
                s1 += __shfl_xor_sync(0xFFFFFFFFu, s1, off);
                s2 += __shfl_xor_sync(0xFFFFFFFFu, s2, off);
                s3 += __shfl_xor_sync(0xFFFFFFFFu, s3, off);
                s4 += __shfl_xor_sync(0xFFFFFFFFu, s4, off);
                s5 += __shfl_xor_sync(0xFFFFFFFFu, s5, off);
            }
            if (lane == 0) {
                const long long base   = (long long)b * K1v + k;
                const long long stride = (long long)Bv * K1v;
                outs[0 * stride + base] = s0 * INV_T;
                outs[1 * stride + base] = s1 * INV_T;
                outs[2 * stride + base] = s2 * INV_T;
                outs[3 * stride + base] = s3 * INV_T;
                outs[4 * stride + base] = s4 * INV_T;
                outs[5 * stride + base] = s5 * INV_T;
                g_over[gw] = 0;               // reset used sentinel
            }
        }
    }

    // ---- self-clean for next launch (VERY END: after all loads issued) ----
    if (lane == 0) g_cw[r] = 0u;
}

// ---------------------------------------------------------------------------
extern "C" void kernel_launch(void* const* d_in, const int* in_sizes, int n_in,
                              void* d_out, int out_size)
{
    const float* l        = (const float*)d_in[0];
    const float* ab       = (const float*)d_in[1];
    const float* ori      = (const float*)d_in[2];
    const float* comp     = (const float*)d_in[3];
    const int*   y        = (const int*)  d_in[4];
    const int*   idx      = (const int*)  d_in[5];
    const float* mem_l    = (const float*)d_in[6];
    const float* mem_ab   = (const float*)d_in[7];
    const float* mem_ori  = (const float*)d_in[8];
    const float* mem_comp = (const float*)d_in[9];

    float* out       = (float*)d_out;
    float* out_outs  = out;
    float* out_banks = out + OUTS_ELEMS;

    build_kernel<<<NBUILD_BLOCKS + Bv, 256>>>(idx, y, l, ab, ori, comp,
                                              mem_l, mem_ab, mem_ori, mem_comp,
                                              out_banks);
    main_kernel<<<NMEM / 8, 256>>>(l, ab, ori, comp,
                                   mem_l, mem_ab, mem_ori, mem_comp,
                                   idx, out_outs, out_banks);
}